// round 6
// baseline (speedup 1.0000x reference)
#include <cuda_runtime.h>
#include <stdint.h>

// DisplaceChannel: out[b,c,y,x] = inp[b,c, y-off_y[p], x-off_x[p]] (p = c/32),
// zero where source out of [0,64). Offsets are multiples of 32 -> 256-bit
// (8-float) vectors are uniformly valid/invalid and 32B-aligned.
//
// R2-winning shape: grid (CH, B), one block per 64x64 plane, 256 threads.
// Each thread owns 2 x float8 (Blackwell 256-bit ld/st), loads front-batched,
// stores streamed (.cs) so the output bypasses L2 and the input stays
// L2-resident across graph replays.

#define CH 288          // 9 * 32
#define H 64
#define W 64
#define W8 8            // float8 per row
#define PLANE8 512      // H * W8

struct f8 { float a0,a1,a2,a3,a4,a5,a6,a7; };

__device__ __forceinline__ f8 ldg256(const float* p) {
    f8 r;
    asm volatile("ld.global.nc.v8.f32 {%0,%1,%2,%3,%4,%5,%6,%7}, [%8];"
                 : "=f"(r.a0), "=f"(r.a1), "=f"(r.a2), "=f"(r.a3),
                   "=f"(r.a4), "=f"(r.a5), "=f"(r.a6), "=f"(r.a7)
                 : "l"(p));
    return r;
}

__device__ __forceinline__ void stg256_cs(float* p, const f8& v) {
    asm volatile("st.global.cs.v8.f32 [%0], {%1,%2,%3,%4,%5,%6,%7,%8};"
                 :: "l"(p),
                    "f"(v.a0), "f"(v.a1), "f"(v.a2), "f"(v.a3),
                    "f"(v.a4), "f"(v.a5), "f"(v.a6), "f"(v.a7)
                 : "memory");
}

__global__ __launch_bounds__(256)
void displace_kernel(const float* __restrict__ in,
                     const int* __restrict__ offsets,
                     float* __restrict__ out)
{
    const int c = blockIdx.x;          // 0..287
    const int b = blockIdx.y;          // 0..15
    const int p = c >> 5;              // position 0..8

    const int off_x = __ldg(&offsets[2 * p]);
    const int off_y = __ldg(&offsets[2 * p + 1]);

    const long base = (((long)b * CH + c) << 9) << 3;   // *PLANE8*8 floats
    const float* __restrict__ src = in + base;
    float* __restrict__ dst = out + base;

    const int t = threadIdx.x;

    f8 v[2];
#pragma unroll
    for (int j = 0; j < 2; j++) {
        const int vid = t + (j << 8);          // 0..511 (float8 units)
        const int x8  = vid & (W8 - 1);
        const int y   = vid >> 3;
        const int sy  = y - off_y;
        const int sx  = (x8 << 3) - off_x;
        v[j].a0=v[j].a1=v[j].a2=v[j].a3=v[j].a4=v[j].a5=v[j].a6=v[j].a7=0.f;
        if ((unsigned)sy < H && (unsigned)sx < W) {
            v[j] = ldg256(&src[(sy << 6) + sx]); // sy*W + sx floats
        }
    }
#pragma unroll
    for (int j = 0; j < 2; j++) {
        stg256_cs(&dst[(t + (j << 8)) << 3], v[j]);
    }
}

extern "C" void kernel_launch(void* const* d_in, const int* in_sizes, int n_in,
                              void* d_out, int out_size)
{
    const float* in = (const float*)d_in[0];
    const int* offsets = (const int*)d_in[1];
    float* out = (float*)d_out;

    dim3 grid(CH, 16);   // (channels, batch) = 4608 blocks
    displace_kernel<<<grid, 256>>>(in, offsets, out);
}

// round 7
// speedup vs baseline: 1.1006x; 1.1006x over previous
#include <cuda_runtime.h>
#include <cuda.h>
#include <stdint.h>

// DisplaceChannel via TMA: out[b,c,y,x] = inp[b,c, y-off_y[p], x-off_x[p]],
// zero where source out of bounds (p = c/32).
//
// One block per (b,c) 64x64 plane. TMA 3D tile load at coords
// (-off_x, -off_y, bc): hardware zero-fills out-of-bounds elements, so the
// boundary masking is free. TMA bulk store back with an L2 evict_first
// cache policy so the output streams past L2 and the input stays
// L2-resident across graph replays (the R2/R4 lesson).

#define CH 288          // 9 * 32
#define B 16
#define H 64
#define W 64
#define TILE_BYTES (H * W * 4)   // 16384

__global__ __launch_bounds__(32)
void displace_tma(const __grid_constant__ CUtensorMap in_map,
                  const __grid_constant__ CUtensorMap out_map,
                  const int* __restrict__ offsets)
{
    __shared__ __align__(128) float tile[H * W];
    __shared__ __align__(8) unsigned long long mbar;

    if (threadIdx.x != 0) return;   // single-thread TMA orchestration

    const int c = blockIdx.x;          // 0..287
    const int b = blockIdx.y;          // 0..15
    const int p = c >> 5;              // position 0..8
    const int bc = b * CH + c;

    const int off_x = __ldg(&offsets[2 * p]);
    const int off_y = __ldg(&offsets[2 * p + 1]);

    const uint32_t tile_a = (uint32_t)__cvta_generic_to_shared(tile);
    const uint32_t mbar_a = (uint32_t)__cvta_generic_to_shared(&mbar);

    asm volatile("mbarrier.init.shared.b64 [%0], 1;" :: "r"(mbar_a));
    asm volatile("fence.proxy.async.shared::cta;" ::: "memory");
    asm volatile("mbarrier.arrive.expect_tx.shared.b64 _, [%0], %1;"
                 :: "r"(mbar_a), "r"((uint32_t)TILE_BYTES));

    // Load source tile; OOB coords are zero-filled by TMA.
    asm volatile(
        "cp.async.bulk.tensor.3d.shared::cta.global.tile.mbarrier::complete_tx::bytes "
        "[%0], [%1, {%2, %3, %4}], [%5];"
        :: "r"(tile_a), "l"(&in_map),
           "r"(-off_x), "r"(-off_y), "r"(bc), "r"(mbar_a)
        : "memory");

    // Wait for load completion (phase 0).
    asm volatile(
        "{\n\t"
        ".reg .pred P;\n"
        "WAIT_%=:\n\t"
        "mbarrier.try_wait.parity.shared::cta.b64 P, [%0], 0;\n\t"
        "@P bra DONE_%=;\n\t"
        "bra WAIT_%=;\n"
        "DONE_%=:\n\t"
        "}"
        :: "r"(mbar_a) : "memory");

    // Store tile to output with evict_first so it streams past L2.
    unsigned long long pol;
    asm volatile("createpolicy.fractional.L2::evict_first.b64 %0, 1.0;" : "=l"(pol));
    asm volatile(
        "cp.async.bulk.tensor.3d.global.shared::cta.tile.bulk_group.L2::cache_hint "
        "[%0, {%1, %2, %3}], [%4], %5;"
        :: "l"(&out_map), "r"(0), "r"(0), "r"(bc), "r"(tile_a), "l"(pol)
        : "memory");
    asm volatile("cp.async.bulk.commit_group;");
    asm volatile("cp.async.bulk.wait_group.read 0;" ::: "memory");
}

// Driver entry point fetched through cudart so we don't need -lcuda at link.
typedef CUresult (*EncodeFn)(
    CUtensorMap*, CUtensorMapDataType, cuuint32_t, void*,
    const cuuint64_t*, const cuuint64_t*, const cuuint32_t*, const cuuint32_t*,
    CUtensorMapInterleave, CUtensorMapSwizzle, CUtensorMapL2promotion,
    CUtensorMapFloatOOBfill);

static void make_map(EncodeFn enc, CUtensorMap* m, void* base)
{
    cuuint64_t dims[3]    = { W, H, (cuuint64_t)B * CH };
    cuuint64_t strides[2] = { W * 4, (cuuint64_t)H * W * 4 };
    cuuint32_t box[3]     = { W, H, 1 };
    cuuint32_t estr[3]    = { 1, 1, 1 };
    enc(m, CU_TENSOR_MAP_DATA_TYPE_FLOAT32, 3, base,
        dims, strides, box, estr,
        CU_TENSOR_MAP_INTERLEAVE_NONE, CU_TENSOR_MAP_SWIZZLE_NONE,
        CU_TENSOR_MAP_L2_PROMOTION_L2_128B, CU_TENSOR_MAP_FLOAT_OOB_FILL_NONE);
}

extern "C" void kernel_launch(void* const* d_in, const int* in_sizes, int n_in,
                              void* d_out, int out_size)
{
    const int* offsets = (const int*)d_in[1];

    EncodeFn enc = nullptr;
    cudaDriverEntryPointQueryResult qr;
    cudaGetDriverEntryPoint("cuTensorMapEncodeTiled", (void**)&enc,
                            cudaEnableDefault, &qr);

    CUtensorMap in_map, out_map;
    make_map(enc, &in_map, (void*)d_in[0]);
    make_map(enc, &out_map, d_out);

    dim3 grid(CH, B);   // one block per (channel, batch) plane
    displace_tma<<<grid, 32>>>(in_map, out_map, offsets);
}